// round 12
// baseline (speedup 1.0000x reference)
#include <cuda_runtime.h>
#include <cuda_bf16.h>
#include <math.h>
#include <stdint.h>

#define BATCH 8
#define TT 96
#define NNODE 200
#define EMB 32
#define HID 32
#define HOR 24
#define FV 400
#define KEV 200
#define KP 208               /* KEV padded to 16 */
#define NSEQ (BATCH*NNODE)   /* 1600 */
#define ROWS (BATCH*TT)      /* 768  */
#define HMT 6400

// ---- scratch (static device globals; no allocations allowed) ----
__device__ float g_E[ROWS*TT];
__device__ __nv_bfloat16 g_attH[ROWS*KP];   // attention hi split
__device__ __nv_bfloat16 g_attL[ROWS*KP];   // attention lo split
__device__ __nv_bfloat16 g_vweH[HMT*KP];    // even v_w cols hi split (2.7MB)
__device__ __nv_bfloat16 g_vweL[HMT*KP];    // lo split
__device__ int   g_zf[BATCH*NNODE];         // per-(b,n) all-masked flag
__device__ float g_colsum[HMT];             // vb + sum of odd v_w columns
__device__ float g_Y[ROWS*HMT];             // mtan output, 19.6 MB
__device__ float g_GI[NSEQ*TT*96];          // gi gates, [seq][t][96], 59 MB

__device__ __forceinline__ float sigf(float x){ return 1.0f/(1.0f + __expf(-x)); }
__device__ __forceinline__ float ftanh(float x){ return 2.0f*sigf(2.0f*x) - 1.0f; }

__device__ __forceinline__ void mma_bf16(float& d0,float& d1,float& d2,float& d3,
    uint32_t a0,uint32_t a1,uint32_t a2,uint32_t a3, uint32_t b0,uint32_t b1){
    asm volatile("mma.sync.aligned.m16n8k16.row.col.f32.bf16.bf16.f32 "
        "{%0,%1,%2,%3}, {%4,%5,%6,%7}, {%8,%9}, {%0,%1,%2,%3};\n"
        : "+f"(d0),"+f"(d1),"+f"(d2),"+f"(d3)
        : "r"(a0),"r"(a1),"r"(a2),"r"(a3), "r"(b0),"r"(b1));
}

// ---------------------------------------------------------------------------
// KQK: fused time-embedding + q/k projection + scores + row-max + E.
// grid=(3, 8) = (32-query slice, batch), 192 threads.
// Each block recomputes te (96x32) and k (96x32) in smem, q for its 32 rows,
// then scores[32x96], row max, E=exp(s-M) -> g_E.
// ---------------------------------------------------------------------------
__global__ void __launch_bounds__(192)
kQK(const float* __restrict__ ts, const float* __restrict__ te_w,
    const float* __restrict__ te_b, const float* __restrict__ q_w,
    const float* __restrict__ q_b, const float* __restrict__ k_w){
    int b = blockIdx.y, q0 = blockIdx.x*32;
    int tid = threadIdx.x;
    __shared__ float te_s[TT][33];
    __shared__ float ks_s[TT][33];
    __shared__ float qs[32][33];
    __shared__ float sc[32][97];

    for (int idx = tid; idx < TT*EMB; idx += 192){
        int row = idx >> 5, e = idx & 31;
        float v = ts[b*TT+row]*te_w[e] + te_b[e];
        if (e > 0) v = sinf(v);
        te_s[row][e] = v;
    }
    __syncthreads();
    for (int idx = tid; idx < TT*EMB; idx += 192){
        int row = idx >> 5, e = idx & 31;
        float k = 0.f;
        #pragma unroll
        for (int i=0;i<EMB;i++) k = fmaf(te_s[row][i], k_w[e*EMB+i], k);
        ks_s[row][e] = k;
    }
    for (int idx = tid; idx < 32*EMB; idx += 192){
        int row = idx >> 5, e = idx & 31;
        float q = q_b[e];
        #pragma unroll
        for (int i=0;i<EMB;i++) q = fmaf(te_s[q0+row][i], q_w[e*EMB+i], q);
        qs[row][e] = q;
    }
    __syncthreads();
    for (int idx = tid; idx < 32*TT; idx += 192){
        int qq = idx / TT, kk = idx - qq*TT;
        float s = 0.f;
        #pragma unroll
        for (int i=0;i<EMB;i++) s = fmaf(qs[qq][i], ks_s[kk][i], s);
        sc[qq][kk] = s * 0.17677669529663687f;
    }
    __syncthreads();
    int w = tid>>5, lane = tid&31;
    for (int r = w; r < 32; r += 6){
        float s0 = sc[r][lane], s1 = sc[r][lane+32], s2 = sc[r][lane+64];
        float m = fmaxf(s0, fmaxf(s1, s2));
        #pragma unroll
        for (int o=16;o;o>>=1) m = fmaxf(m, __shfl_xor_sync(0xffffffffu, m, o));
        float* er = g_E + ((size_t)b*TT + q0 + r)*TT;
        er[lane]    = __expf(s0 - m);
        er[lane+32] = __expf(s1 - m);
        er[lane+64] = __expf(s2 - m);
    }
}

// ---------------------------------------------------------------------------
// K2: masked softmax aggregation, query-split for occupancy.
// grid=(25, 8, 3). Warp w = node n0+w, lane = one query.
// Writes bf16 hi/lo splits of attention output.
// ---------------------------------------------------------------------------
__global__ void __launch_bounds__(256)
k2_att(const float* __restrict__ x, const float* __restrict__ mask){
    int b = blockIdx.y, n0 = blockIdx.x*8, q0 = blockIdx.z*32;
    int tid = threadIdx.x, w = tid>>5, lane = tid&31;
    int n = n0 + w;
    __shared__ float Es[32][97];
    __shared__ float xs[TT][9];
    __shared__ float ms[TT][9];
    __shared__ float ssx[8];
    const float* xb = x    + (size_t)b*TT*NNODE + n0;
    const float* mb = mask + (size_t)b*TT*NNODE + n0;
    for (int idx = tid; idx < TT*8; idx += 256){
        int t = idx>>3, i = idx&7;
        xs[t][i] = xb[t*NNODE + i];
        ms[t][i] = mb[t*NNODE + i];
    }
    for (int q=w; q<32; q+=8){
        const float* er = g_E + ((size_t)b*TT + q0 + q)*TT;
        Es[q][lane]    = er[lane];
        Es[q][lane+32] = er[lane+32];
        Es[q][lane+64] = er[lane+64];
    }
    __syncthreads();
    float sx = 0.f;
    #pragma unroll
    for (int t=lane; t<TT; t+=32) sx += xs[t][w];
    #pragma unroll
    for (int o=16;o;o>>=1) sx += __shfl_xor_sync(0xffffffffu, sx, o);
    if (lane==0) ssx[w] = sx;
    __syncwarp();

    float num=0.f, den=0.f;
    #pragma unroll 4
    for (int k=0;k<TT;k++){
        float mm = ms[k][w];
        float mx = mm * xs[k][w];
        float e  = Es[lane][k];
        den += e*mm;
        num  = fmaf(e, mx, num);
    }
    bool nz = (den > 0.f);
    float v = nz ? num/den : ssx[w]*(1.0f/96.0f);
    __nv_bfloat16 hi = __float2bfloat16(v);
    __nv_bfloat16 lo = __float2bfloat16(v - __bfloat162float(hi));
    size_t row = (size_t)b*TT + q0 + lane;
    g_attH[row*KP + n] = hi;
    g_attL[row*KP + n] = lo;
    if (lane==0 && blockIdx.z==0) g_zf[b*NNODE + n] = nz ? 0 : 1;
}

// ---------------------------------------------------------------------------
// K2b: pack even v_w columns as bf16 hi/lo splits; colsum = vb + sum(odd).
// Warps j<768 additionally zero the K-pad columns of att row j.
// ---------------------------------------------------------------------------
__global__ void k2b_pack(const float* __restrict__ vw, const float* __restrict__ vb){
    int j = (blockIdx.x*256 + threadIdx.x) >> 5;
    int lane = threadIdx.x & 31;
    const float4* src = (const float4*)(vw + (size_t)j*FV);
    float os = 0.f;
    #pragma unroll
    for (int c=lane; c<100; c+=32){
        float4 v = src[c];
        __nv_bfloat16 h0 = __float2bfloat16(v.x);
        __nv_bfloat16 h1 = __float2bfloat16(v.z);
        g_vweH[(size_t)j*KP + 2*c]   = h0;
        g_vweH[(size_t)j*KP + 2*c+1] = h1;
        g_vweL[(size_t)j*KP + 2*c]   = __float2bfloat16(v.x - __bfloat162float(h0));
        g_vweL[(size_t)j*KP + 2*c+1] = __float2bfloat16(v.z - __bfloat162float(h1));
        os += v.y + v.w;
    }
    if (lane < 8){
        g_vweH[(size_t)j*KP + 200 + lane] = __float2bfloat16(0.f);
        g_vweL[(size_t)j*KP + 200 + lane] = __float2bfloat16(0.f);
    }
    if (j < ROWS){
        if (lane < 8)       g_attH[(size_t)j*KP + 200 + lane] = __float2bfloat16(0.f);
        else if (lane < 16) g_attL[(size_t)j*KP + 200 + (lane-8)] = __float2bfloat16(0.f);
    }
    #pragma unroll
    for (int o=16;o;o>>=1) os += __shfl_xor_sync(0xffffffffu, os, o);
    if (lane == 0) g_colsum[j] = vb[j] + os;
}

// ---------------------------------------------------------------------------
// K3: Y[768x6400] = att[768x208] @ vwe[6400x208]^T + colsum
// bf16 3-term split GEMM (hh + hl + lh), preconverted operands.
// Single-buffered smem + register-staged prefetch. Unchanged from R10.
// ---------------------------------------------------------------------------
__global__ void __launch_bounds__(256)
k3_vgemm_bf(){
    __shared__ uint32_t AsH[128][12];
    __shared__ uint32_t AsL[128][12];
    __shared__ uint32_t BsH[128][12];
    __shared__ uint32_t BsL[128][12];
    __shared__ float csh[128];
    int tid = threadIdx.x;
    int bn = blockIdx.x, bm = blockIdx.y;
    int warp = tid>>5, lane = tid&31;
    int wm = warp>>2, wn = warp&3;
    int g = lane>>2, c = lane&3;

    int lrow = tid>>1;
    int half = tid&1;

    const uint4* AgH = (const uint4*)(g_attH + (size_t)(bm*128 + lrow)*KP);
    const uint4* AgL = (const uint4*)(g_attL + (size_t)(bm*128 + lrow)*KP);
    const uint4* BgH = (const uint4*)(g_vweH + (size_t)(bn*128 + lrow)*KP);
    const uint4* BgL = (const uint4*)(g_vweL + (size_t)(bn*128 + lrow)*KP);

    if (tid < 128) csh[tid] = g_colsum[bn*128 + tid];

    uint4 ah_st = AgH[half], al_st = AgL[half];
    uint4 bh_st = BgH[half], bl_st = BgL[half];
    *(uint4*)&AsH[lrow][half*4] = ah_st;
    *(uint4*)&AsL[lrow][half*4] = al_st;
    *(uint4*)&BsH[lrow][half*4] = bh_st;
    *(uint4*)&BsL[lrow][half*4] = bl_st;
    __syncthreads();

    float acc[4][4][4];
    #pragma unroll
    for (int i=0;i<4;i++)
        #pragma unroll
        for (int j=0;j<4;j++)
            #pragma unroll
            for (int r=0;r<4;r++) acc[i][j][r]=0.f;

    #pragma unroll 1
    for (int it=0; it<13; ++it){
        if (it < 12){
            ah_st = AgH[(it+1)*2 + half]; al_st = AgL[(it+1)*2 + half];
            bh_st = BgH[(it+1)*2 + half]; bl_st = BgL[(it+1)*2 + half];
        }
        uint32_t aH[4][4], aL[4][4], bH[4][2], bL[4][2];
        #pragma unroll
        for (int mt=0; mt<4; mt++){
            int rb = wm*64 + mt*16 + g;
            aH[mt][0]=AsH[rb  ][c];   aH[mt][1]=AsH[rb+8][c];
            aH[mt][2]=AsH[rb  ][c+4]; aH[mt][3]=AsH[rb+8][c+4];
            aL[mt][0]=AsL[rb  ][c];   aL[mt][1]=AsL[rb+8][c];
            aL[mt][2]=AsL[rb  ][c+4]; aL[mt][3]=AsL[rb+8][c+4];
        }
        #pragma unroll
        for (int nt=0; nt<4; nt++){
            int nb = wn*32 + nt*8 + g;
            bH[nt][0]=BsH[nb][c]; bH[nt][1]=BsH[nb][c+4];
            bL[nt][0]=BsL[nb][c]; bL[nt][1]=BsL[nb][c+4];
        }
        #pragma unroll
        for (int mt=0; mt<4; mt++)
            #pragma unroll
            for (int nt=0; nt<4; nt++){
                float* d = acc[mt][nt];
                mma_bf16(d[0],d[1],d[2],d[3],
                         aH[mt][0],aH[mt][1],aH[mt][2],aH[mt][3],
                         bL[nt][0],bL[nt][1]);
                mma_bf16(d[0],d[1],d[2],d[3],
                         aL[mt][0],aL[mt][1],aL[mt][2],aL[mt][3],
                         bH[nt][0],bH[nt][1]);
                mma_bf16(d[0],d[1],d[2],d[3],
                         aH[mt][0],aH[mt][1],aH[mt][2],aH[mt][3],
                         bH[nt][0],bH[nt][1]);
            }
        if (it < 12){
            __syncthreads();
            *(uint4*)&AsH[lrow][half*4] = ah_st;
            *(uint4*)&AsL[lrow][half*4] = al_st;
            *(uint4*)&BsH[lrow][half*4] = bh_st;
            *(uint4*)&BsL[lrow][half*4] = bl_st;
            __syncthreads();
        }
    }

    #pragma unroll
    for (int mt=0; mt<4; mt++){
        #pragma unroll
        for (int nt=0; nt<4; nt++){
            int colL = wn*32 + nt*8 + 2*c;
            int col  = bn*128 + colL;
            float cs0 = csh[colL], cs1 = csh[colL+1];
            int r0 = bm*128 + wm*64 + mt*16 + g;
            float* d = acc[mt][nt];
            *(float2*)(g_Y + (size_t)r0*HMT + col) =
                make_float2(d[0]+cs0, d[1]+cs1);
            *(float2*)(g_Y + (size_t)(r0+8)*HMT + col) =
                make_float2(d[2]+cs0, d[3]+cs1);
        }
    }
}

// ---------------------------------------------------------------------------
// KGI: input-gate projection, parallel over (seq, t-chunk).
// warp = (seq, chunk of 12 timesteps); grid = 1600 x 256 (12800 warps).
// ---------------------------------------------------------------------------
#define TCH 12
__global__ void __launch_bounds__(256)
kGI(const float* __restrict__ wih, const float* __restrict__ bih,
    const float* __restrict__ vw){
    int gw = blockIdx.x*8 + (threadIdx.x>>5);    // 0..12799
    int j  = threadIdx.x & 31;
    int seq = gw >> 3;
    int tc  = gw & 7;
    int t0  = tc * TCH;
    int b = seq / NNODE, n = seq % NNODE;

    float wr[32], wz[32], wn[32];
    #pragma unroll
    for (int i=0;i<32;i++){
        wr[i] = wih[j*32+i];
        wz[i] = wih[(32+j)*32+i];
        wn[i] = wih[(64+j)*32+i];
    }

    float c0=0.f, c1=0.f, c2=0.f;
    {
        int anyz = 0;
        for (int i=j; i<NNODE; i+=32) anyz |= g_zf[b*NNODE+i];
        anyz = __reduce_or_sync(0xffffffffu, anyz);
        if (anyz){
            for (int n0=0;n0<NNODE;n0++){
                if (g_zf[b*NNODE+n0]){
                    #pragma unroll
                    for (int i=0;i<32;i++){
                        float vv = vw[((size_t)n*32+i)*FV + 2*n0 + 1];
                        c0 = fmaf(wr[i], vv, c0);
                        c1 = fmaf(wz[i], vv, c1);
                        c2 = fmaf(wn[i], vv, c2);
                    }
                }
            }
        }
    }
    float br  = bih[j]    - c0;
    float bz  = bih[32+j] - c1;
    float bnn = bih[64+j] - c2;

    const float* xb = g_Y + (size_t)b*TT*HMT + n*HID + j + (size_t)t0*HMT;
    float* gp = g_GI + (size_t)seq*TT*96 + t0*96;

    float xq[2];
    xq[0] = xb[0];
    xq[1] = xb[HMT];

    #pragma unroll
    for (int t=0;t<TCH;t++){
        float xc = xq[t&1];
        if (t+2 < TCH) xq[t&1] = xb[(size_t)(t+2)*HMT];
        float gr=br, gz=bz, gn=bnn;
        #pragma unroll
        for (int i=0;i<32;i++){
            float xv = __shfl_sync(0xffffffffu, xc, i);
            gr = fmaf(wr[i], xv, gr);
            gz = fmaf(wz[i], xv, gz);
            gn = fmaf(wn[i], xv, gn);
        }
        gp[t*96 +      j] = gr;
        gp[t*96 + 32 + j] = gz;
        gp[t*96 + 64 + j] = gn;
    }
}

// ---------------------------------------------------------------------------
// K5: lean GRU recurrence + fused MLP decoder.
// ---------------------------------------------------------------------------
__global__ void __launch_bounds__(128)
k5_gru(const float* __restrict__ whh, const float* __restrict__ bhh,
       const float* __restrict__ mlp_w, const float* __restrict__ mlp_b,
       const float* __restrict__ out_w, const float* __restrict__ out_b,
       float* __restrict__ out){
    int wid = threadIdx.x >> 5;
    int j   = threadIdx.x & 31;
    int seq = blockIdx.x*4 + wid;
    int b = seq / NNODE, n = seq % NNODE;

    float ur[32], uz[32], un[32];
    #pragma unroll
    for (int i=0;i<32;i++){
        ur[i] = whh[j*32+i];
        uz[i] = whh[(32+j)*32+i];
        un[i] = whh[(64+j)*32+i];
    }
    float bhr = bhh[j], bhz = bhh[32+j], bhn = bhh[64+j];

    const float* gp = g_GI + (size_t)seq*TT*96;
    float a0 = gp[j], a1 = gp[32+j], a2 = gp[64+j];

    float h = 0.f;
    #pragma unroll 2
    for (int t=0;t<TT;t++){
        const float* nx = gp + ((t<TT-1)? t+1 : t)*96;
        float p0 = nx[j], p1 = nx[32+j], p2 = nx[64+j];
        float hr=0.f, hz=0.f, hn=0.f;
        #pragma unroll
        for (int i=0;i<32;i++){
            float hv = __shfl_sync(0xffffffffu, h, i);
            hr = fmaf(ur[i], hv, hr);
            hz = fmaf(uz[i], hv, hz);
            hn = fmaf(un[i], hv, hn);
        }
        float r  = sigf(a0 + hr + bhr);
        float z  = sigf(a1 + hz + bhz);
        float nn = ftanh(a2 + r*(hn + bhn));
        h = (1.f - z)*nn + z*h;
        a0 = p0; a1 = p1; a2 = p2;
    }

    float h2 = mlp_b[j];
    #pragma unroll
    for (int i=0;i<32;i++)
        h2 = fmaf(mlp_w[j*32+i], __shfl_sync(0xffffffffu, h, i), h2);
    h2 = fmaxf(h2, 0.f);

    float y = (j < HOR) ? out_b[j] : 0.f;
    #pragma unroll
    for (int i=0;i<32;i++){
        float v = __shfl_sync(0xffffffffu, h2, i);
        if (j < HOR) y = fmaf(out_w[j*32+i], v, y);
    }
    if (j < HOR) out[((size_t)b*HOR + j)*NNODE + n] = y;
}

// ---------------------------------------------------------------------------
extern "C" void kernel_launch(void* const* d_in, const int* in_sizes, int n_in,
                              void* d_out, int out_size){
    const float* x    = (const float*)d_in[0];
    const float* mask = (const float*)d_in[2];
    const float* ts   = (const float*)d_in[3];
    const float* te_w = (const float*)d_in[4];
    const float* te_b = (const float*)d_in[5];
    const float* q_w  = (const float*)d_in[6];
    const float* q_b  = (const float*)d_in[7];
    const float* k_w  = (const float*)d_in[8];
    const float* v_w  = (const float*)d_in[9];
    const float* v_b  = (const float*)d_in[10];
    const float* wih  = (const float*)d_in[11];
    const float* whh  = (const float*)d_in[12];
    const float* bih  = (const float*)d_in[13];
    const float* bhh  = (const float*)d_in[14];
    const float* mlpw = (const float*)d_in[15];
    const float* mlpb = (const float*)d_in[16];
    const float* outw = (const float*)d_in[17];
    const float* outb = (const float*)d_in[18];
    float* out = (float*)d_out;

    kQK<<<dim3(3, BATCH), 192>>>(ts, te_w, te_b, q_w, q_b, k_w);
    k2b_pack<<<800, 256>>>(v_w, v_b);
    k2_att<<<dim3(25, BATCH, 3), 256>>>(x, mask);
    k3_vgemm_bf<<<dim3(HMT/128, ROWS/128), 256>>>();
    kGI<<<1600, 256>>>(wih, bih, v_w);
    k5_gru<<<NSEQ/4, 128>>>(whh, bhh, mlpw, mlpb, outw, outb, out);
}

// round 13
// speedup vs baseline: 1.8385x; 1.8385x over previous
#include <cuda_runtime.h>
#include <cuda_bf16.h>
#include <math.h>
#include <stdint.h>

#define BATCH 8
#define TT 96
#define NNODE 200
#define EMB 32
#define HID 32
#define HOR 24
#define FV 400
#define KEV 200
#define KP 208               /* KEV padded to 16 */
#define NSEQ (BATCH*NNODE)   /* 1600 */
#define ROWS (BATCH*TT)      /* 768  */
#define HMT 6400

// ---- scratch (static device globals; no allocations allowed) ----
__device__ float g_E[ROWS*TT];
__device__ __nv_bfloat16 g_attH[ROWS*KP];   // attention hi split
__device__ __nv_bfloat16 g_attL[ROWS*KP];   // attention lo split
__device__ __nv_bfloat16 g_vweH[HMT*KP];    // even v_w cols hi split (2.7MB)
__device__ __nv_bfloat16 g_vweL[HMT*KP];    // lo split
__device__ int   g_zf[BATCH*NNODE];         // per-(b,n) all-masked flag
__device__ float g_colsum[HMT];             // vb + sum of odd v_w columns
__device__ float g_Y[ROWS*HMT];             // mtan output, 19.6 MB
__device__ float g_GI[NSEQ*TT*96];          // gi gates, [seq][t][96], 59 MB

__device__ __forceinline__ float sigf(float x){ return 1.0f/(1.0f + __expf(-x)); }
__device__ __forceinline__ float ftanh(float x){ return 2.0f*sigf(2.0f*x) - 1.0f; }

__device__ __forceinline__ void mma_bf16(float& d0,float& d1,float& d2,float& d3,
    uint32_t a0,uint32_t a1,uint32_t a2,uint32_t a3, uint32_t b0,uint32_t b1){
    asm volatile("mma.sync.aligned.m16n8k16.row.col.f32.bf16.bf16.f32 "
        "{%0,%1,%2,%3}, {%4,%5,%6,%7}, {%8,%9}, {%0,%1,%2,%3};\n"
        : "+f"(d0),"+f"(d1),"+f"(d2),"+f"(d3)
        : "r"(a0),"r"(a1),"r"(a2),"r"(a3), "r"(b0),"r"(b1));
}

// ---------------------------------------------------------------------------
// KQK: fused time-embedding + q/k projection + scores + row-max + E.
// grid=(3, 8) = (32-query slice, batch), 192 threads.
// ---------------------------------------------------------------------------
__global__ void __launch_bounds__(192)
kQK(const float* __restrict__ ts, const float* __restrict__ te_w,
    const float* __restrict__ te_b, const float* __restrict__ q_w,
    const float* __restrict__ q_b, const float* __restrict__ k_w){
    int b = blockIdx.y, q0 = blockIdx.x*32;
    int tid = threadIdx.x;
    __shared__ float te_s[TT][33];
    __shared__ float ks_s[TT][33];
    __shared__ float qs[32][33];
    __shared__ float sc[32][97];

    for (int idx = tid; idx < TT*EMB; idx += 192){
        int row = idx >> 5, e = idx & 31;
        float v = ts[b*TT+row]*te_w[e] + te_b[e];
        if (e > 0) v = sinf(v);
        te_s[row][e] = v;
    }
    __syncthreads();
    for (int idx = tid; idx < TT*EMB; idx += 192){
        int row = idx >> 5, e = idx & 31;
        float k = 0.f;
        #pragma unroll
        for (int i=0;i<EMB;i++) k = fmaf(te_s[row][i], k_w[e*EMB+i], k);
        ks_s[row][e] = k;
    }
    for (int idx = tid; idx < 32*EMB; idx += 192){
        int row = idx >> 5, e = idx & 31;
        float q = q_b[e];
        #pragma unroll
        for (int i=0;i<EMB;i++) q = fmaf(te_s[q0+row][i], q_w[e*EMB+i], q);
        qs[row][e] = q;
    }
    __syncthreads();
    for (int idx = tid; idx < 32*TT; idx += 192){
        int qq = idx / TT, kk = idx - qq*TT;
        float s = 0.f;
        #pragma unroll
        for (int i=0;i<EMB;i++) s = fmaf(qs[qq][i], ks_s[kk][i], s);
        sc[qq][kk] = s * 0.17677669529663687f;
    }
    __syncthreads();
    int w = tid>>5, lane = tid&31;
    for (int r = w; r < 32; r += 6){
        float s0 = sc[r][lane], s1 = sc[r][lane+32], s2 = sc[r][lane+64];
        float m = fmaxf(s0, fmaxf(s1, s2));
        #pragma unroll
        for (int o=16;o;o>>=1) m = fmaxf(m, __shfl_xor_sync(0xffffffffu, m, o));
        float* er = g_E + ((size_t)b*TT + q0 + r)*TT;
        er[lane]    = __expf(s0 - m);
        er[lane+32] = __expf(s1 - m);
        er[lane+64] = __expf(s2 - m);
    }
}

// ---------------------------------------------------------------------------
// K2: masked softmax aggregation, query-split for occupancy.
// grid=(25, 8, 3). Warp w = node n0+w, lane = one query.
// ---------------------------------------------------------------------------
__global__ void __launch_bounds__(256)
k2_att(const float* __restrict__ x, const float* __restrict__ mask){
    int b = blockIdx.y, n0 = blockIdx.x*8, q0 = blockIdx.z*32;
    int tid = threadIdx.x, w = tid>>5, lane = tid&31;
    int n = n0 + w;
    __shared__ float Es[32][97];
    __shared__ float xs[TT][9];
    __shared__ float ms[TT][9];
    __shared__ float ssx[8];
    const float* xb = x    + (size_t)b*TT*NNODE + n0;
    const float* mb = mask + (size_t)b*TT*NNODE + n0;
    for (int idx = tid; idx < TT*8; idx += 256){
        int t = idx>>3, i = idx&7;
        xs[t][i] = xb[t*NNODE + i];
        ms[t][i] = mb[t*NNODE + i];
    }
    for (int q=w; q<32; q+=8){
        const float* er = g_E + ((size_t)b*TT + q0 + q)*TT;
        Es[q][lane]    = er[lane];
        Es[q][lane+32] = er[lane+32];
        Es[q][lane+64] = er[lane+64];
    }
    __syncthreads();
    float sx = 0.f;
    #pragma unroll
    for (int t=lane; t<TT; t+=32) sx += xs[t][w];
    #pragma unroll
    for (int o=16;o;o>>=1) sx += __shfl_xor_sync(0xffffffffu, sx, o);
    if (lane==0) ssx[w] = sx;
    __syncwarp();

    float num=0.f, den=0.f;
    #pragma unroll 4
    for (int k=0;k<TT;k++){
        float mm = ms[k][w];
        float mx = mm * xs[k][w];
        float e  = Es[lane][k];
        den += e*mm;
        num  = fmaf(e, mx, num);
    }
    bool nz = (den > 0.f);
    float v = nz ? num/den : ssx[w]*(1.0f/96.0f);
    __nv_bfloat16 hi = __float2bfloat16(v);
    __nv_bfloat16 lo = __float2bfloat16(v - __bfloat162float(hi));
    size_t row = (size_t)b*TT + q0 + lane;
    g_attH[row*KP + n] = hi;
    g_attL[row*KP + n] = lo;
    if (lane==0 && blockIdx.z==0) g_zf[b*NNODE + n] = nz ? 0 : 1;
}

// ---------------------------------------------------------------------------
// K2b: pack even v_w columns as bf16 hi/lo splits; colsum = vb + sum(odd).
// Warps j<768 additionally zero the K-pad columns of att row j.
// ---------------------------------------------------------------------------
__global__ void k2b_pack(const float* __restrict__ vw, const float* __restrict__ vb){
    int j = (blockIdx.x*256 + threadIdx.x) >> 5;
    int lane = threadIdx.x & 31;
    const float4* src = (const float4*)(vw + (size_t)j*FV);
    float os = 0.f;
    #pragma unroll
    for (int c=lane; c<100; c+=32){
        float4 v = src[c];
        __nv_bfloat16 h0 = __float2bfloat16(v.x);
        __nv_bfloat16 h1 = __float2bfloat16(v.z);
        g_vweH[(size_t)j*KP + 2*c]   = h0;
        g_vweH[(size_t)j*KP + 2*c+1] = h1;
        g_vweL[(size_t)j*KP + 2*c]   = __float2bfloat16(v.x - __bfloat162float(h0));
        g_vweL[(size_t)j*KP + 2*c+1] = __float2bfloat16(v.z - __bfloat162float(h1));
        os += v.y + v.w;
    }
    if (lane < 8){
        g_vweH[(size_t)j*KP + 200 + lane] = __float2bfloat16(0.f);
        g_vweL[(size_t)j*KP + 200 + lane] = __float2bfloat16(0.f);
    }
    if (j < ROWS){
        if (lane < 8)       g_attH[(size_t)j*KP + 200 + lane] = __float2bfloat16(0.f);
        else if (lane < 16) g_attL[(size_t)j*KP + 200 + (lane-8)] = __float2bfloat16(0.f);
    }
    #pragma unroll
    for (int o=16;o;o>>=1) os += __shfl_xor_sync(0xffffffffu, os, o);
    if (lane == 0) g_colsum[j] = vb[j] + os;
}

// ---------------------------------------------------------------------------
// K3: Y[768x6400] = att[768x208] @ vwe[6400x208]^T + colsum
// bf16 3-term split GEMM. Single-buffered smem + register-staged prefetch.
// __launch_bounds__(256,2): cap regs at 128 for 2 CTAs/SM.
// ---------------------------------------------------------------------------
__global__ void __launch_bounds__(256,2)
k3_vgemm_bf(){
    __shared__ uint32_t AsH[128][12];
    __shared__ uint32_t AsL[128][12];
    __shared__ uint32_t BsH[128][12];
    __shared__ uint32_t BsL[128][12];
    __shared__ float csh[128];
    int tid = threadIdx.x;
    int bn = blockIdx.x, bm = blockIdx.y;
    int warp = tid>>5, lane = tid&31;
    int wm = warp>>2, wn = warp&3;
    int g = lane>>2, c = lane&3;

    int lrow = tid>>1;
    int half = tid&1;

    const uint4* AgH = (const uint4*)(g_attH + (size_t)(bm*128 + lrow)*KP);
    const uint4* AgL = (const uint4*)(g_attL + (size_t)(bm*128 + lrow)*KP);
    const uint4* BgH = (const uint4*)(g_vweH + (size_t)(bn*128 + lrow)*KP);
    const uint4* BgL = (const uint4*)(g_vweL + (size_t)(bn*128 + lrow)*KP);

    if (tid < 128) csh[tid] = g_colsum[bn*128 + tid];

    uint4 ah_st = AgH[half], al_st = AgL[half];
    uint4 bh_st = BgH[half], bl_st = BgL[half];
    *(uint4*)&AsH[lrow][half*4] = ah_st;
    *(uint4*)&AsL[lrow][half*4] = al_st;
    *(uint4*)&BsH[lrow][half*4] = bh_st;
    *(uint4*)&BsL[lrow][half*4] = bl_st;
    __syncthreads();

    float acc[4][4][4];
    #pragma unroll
    for (int i=0;i<4;i++)
        #pragma unroll
        for (int j=0;j<4;j++)
            #pragma unroll
            for (int r=0;r<4;r++) acc[i][j][r]=0.f;

    #pragma unroll 1
    for (int it=0; it<13; ++it){
        if (it < 12){
            ah_st = AgH[(it+1)*2 + half]; al_st = AgL[(it+1)*2 + half];
            bh_st = BgH[(it+1)*2 + half]; bl_st = BgL[(it+1)*2 + half];
        }
        uint32_t aH[4][4], aL[4][4], bH[4][2], bL[4][2];
        #pragma unroll
        for (int mt=0; mt<4; mt++){
            int rb = wm*64 + mt*16 + g;
            aH[mt][0]=AsH[rb  ][c];   aH[mt][1]=AsH[rb+8][c];
            aH[mt][2]=AsH[rb  ][c+4]; aH[mt][3]=AsH[rb+8][c+4];
            aL[mt][0]=AsL[rb  ][c];   aL[mt][1]=AsL[rb+8][c];
            aL[mt][2]=AsL[rb  ][c+4]; aL[mt][3]=AsL[rb+8][c+4];
        }
        #pragma unroll
        for (int nt=0; nt<4; nt++){
            int nb = wn*32 + nt*8 + g;
            bH[nt][0]=BsH[nb][c]; bH[nt][1]=BsH[nb][c+4];
            bL[nt][0]=BsL[nb][c]; bL[nt][1]=BsL[nb][c+4];
        }
        #pragma unroll
        for (int mt=0; mt<4; mt++)
            #pragma unroll
            for (int nt=0; nt<4; nt++){
                float* d = acc[mt][nt];
                mma_bf16(d[0],d[1],d[2],d[3],
                         aH[mt][0],aH[mt][1],aH[mt][2],aH[mt][3],
                         bL[nt][0],bL[nt][1]);
                mma_bf16(d[0],d[1],d[2],d[3],
                         aL[mt][0],aL[mt][1],aL[mt][2],aL[mt][3],
                         bH[nt][0],bH[nt][1]);
                mma_bf16(d[0],d[1],d[2],d[3],
                         aH[mt][0],aH[mt][1],aH[mt][2],aH[mt][3],
                         bH[nt][0],bH[nt][1]);
            }
        if (it < 12){
            __syncthreads();
            *(uint4*)&AsH[lrow][half*4] = ah_st;
            *(uint4*)&AsL[lrow][half*4] = al_st;
            *(uint4*)&BsH[lrow][half*4] = bh_st;
            *(uint4*)&BsL[lrow][half*4] = bl_st;
            __syncthreads();
        }
    }

    #pragma unroll
    for (int mt=0; mt<4; mt++){
        #pragma unroll
        for (int nt=0; nt<4; nt++){
            int colL = wn*32 + nt*8 + 2*c;
            int col  = bn*128 + colL;
            float cs0 = csh[colL], cs1 = csh[colL+1];
            int r0 = bm*128 + wm*64 + mt*16 + g;
            float* d = acc[mt][nt];
            *(float2*)(g_Y + (size_t)r0*HMT + col) =
                make_float2(d[0]+cs0, d[1]+cs1);
            *(float2*)(g_Y + (size_t)(r0+8)*HMT + col) =
                make_float2(d[2]+cs0, d[3]+cs1);
        }
    }
}

// ---------------------------------------------------------------------------
// KGI: input-gate projection. block = one seq, 8 warps x 12-step chunks.
// wih staged via padded smem -> coalesced global load + conflict-free LDS.
// ---------------------------------------------------------------------------
#define TCH 12
__global__ void __launch_bounds__(256)
kGI(const float* __restrict__ wih, const float* __restrict__ bih,
    const float* __restrict__ vw){
    __shared__ float wsh[96][33];       // 12.4 KB, padded
    int tid = threadIdx.x;
    for (int idx = tid; idx < 96*32; idx += 256)
        wsh[idx>>5][idx&31] = wih[idx];
    __syncthreads();

    int w = tid>>5, j = tid&31;
    int seq = blockIdx.x;
    int t0  = w * TCH;
    int b = seq / NNODE, n = seq % NNODE;

    float wr[32], wz[32], wn[32];
    #pragma unroll
    for (int i=0;i<32;i++){
        wr[i] = wsh[j][i];
        wz[i] = wsh[32+j][i];
        wn[i] = wsh[64+j][i];
    }

    // all-masked-node correction (exact; probability ~2^-96 per node)
    float c0=0.f, c1=0.f, c2=0.f;
    {
        int anyz = 0;
        for (int i=j; i<NNODE; i+=32) anyz |= g_zf[b*NNODE+i];
        anyz = __reduce_or_sync(0xffffffffu, anyz);
        if (anyz){
            for (int n0=0;n0<NNODE;n0++){
                if (g_zf[b*NNODE+n0]){
                    #pragma unroll
                    for (int i=0;i<32;i++){
                        float vv = vw[((size_t)n*32+i)*FV + 2*n0 + 1];
                        c0 = fmaf(wr[i], vv, c0);
                        c1 = fmaf(wz[i], vv, c1);
                        c2 = fmaf(wn[i], vv, c2);
                    }
                }
            }
        }
    }
    float br  = bih[j]    - c0;
    float bz  = bih[32+j] - c1;
    float bnn = bih[64+j] - c2;

    const float* xb = g_Y + (size_t)b*TT*HMT + n*HID + j + (size_t)t0*HMT;
    float* gp = g_GI + (size_t)seq*TT*96 + t0*96;

    float xq[2];
    xq[0] = xb[0];
    xq[1] = xb[HMT];

    #pragma unroll
    for (int t=0;t<TCH;t++){
        float xc = xq[t&1];
        if (t+2 < TCH) xq[t&1] = xb[(size_t)(t+2)*HMT];
        float gr=br, gz=bz, gn=bnn;
        #pragma unroll
        for (int i=0;i<32;i++){
            float xv = __shfl_sync(0xffffffffu, xc, i);
            gr = fmaf(wr[i], xv, gr);
            gz = fmaf(wz[i], xv, gz);
            gn = fmaf(wn[i], xv, gn);
        }
        gp[t*96 +      j] = gr;
        gp[t*96 + 32 + j] = gz;
        gp[t*96 + 64 + j] = gn;
    }
}

// ---------------------------------------------------------------------------
// K5: lean GRU recurrence + fused MLP decoder.
// whh staged via padded smem (coalesced + conflict-free).
// ---------------------------------------------------------------------------
__global__ void __launch_bounds__(128)
k5_gru(const float* __restrict__ whh, const float* __restrict__ bhh,
       const float* __restrict__ mlp_w, const float* __restrict__ mlp_b,
       const float* __restrict__ out_w, const float* __restrict__ out_b,
       float* __restrict__ out){
    __shared__ float ush[96][33];       // 12.4 KB, padded
    int tid = threadIdx.x;
    for (int idx = tid; idx < 96*32; idx += 128)
        ush[idx>>5][idx&31] = whh[idx];
    __syncthreads();

    int wid = tid >> 5;
    int j   = tid & 31;
    int seq = blockIdx.x*4 + wid;
    int b = seq / NNODE, n = seq % NNODE;

    float ur[32], uz[32], un[32];
    #pragma unroll
    for (int i=0;i<32;i++){
        ur[i] = ush[j][i];
        uz[i] = ush[32+j][i];
        un[i] = ush[64+j][i];
    }
    float bhr = bhh[j], bhz = bhh[32+j], bhn = bhh[64+j];

    const float* gp = g_GI + (size_t)seq*TT*96;
    float a0 = gp[j], a1 = gp[32+j], a2 = gp[64+j];

    float h = 0.f;
    #pragma unroll 2
    for (int t=0;t<TT;t++){
        const float* nx = gp + ((t<TT-1)? t+1 : t)*96;
        float p0 = nx[j], p1 = nx[32+j], p2 = nx[64+j];
        float hr=0.f, hz=0.f, hn=0.f;
        #pragma unroll
        for (int i=0;i<32;i++){
            float hv = __shfl_sync(0xffffffffu, h, i);
            hr = fmaf(ur[i], hv, hr);
            hz = fmaf(uz[i], hv, hz);
            hn = fmaf(un[i], hv, hn);
        }
        float r  = sigf(a0 + hr + bhr);
        float z  = sigf(a1 + hz + bhz);
        float nn = ftanh(a2 + r*(hn + bhn));
        h = (1.f - z)*nn + z*h;
        a0 = p0; a1 = p1; a2 = p2;
    }

    float h2 = mlp_b[j];
    #pragma unroll
    for (int i=0;i<32;i++)
        h2 = fmaf(mlp_w[j*32+i], __shfl_sync(0xffffffffu, h, i), h2);
    h2 = fmaxf(h2, 0.f);

    float y = (j < HOR) ? out_b[j] : 0.f;
    #pragma unroll
    for (int i=0;i<32;i++){
        float v = __shfl_sync(0xffffffffu, h2, i);
        if (j < HOR) y = fmaf(out_w[j*32+i], v, y);
    }
    if (j < HOR) out[((size_t)b*HOR + j)*NNODE + n] = y;
}

// ---------------------------------------------------------------------------
extern "C" void kernel_launch(void* const* d_in, const int* in_sizes, int n_in,
                              void* d_out, int out_size){
    const float* x    = (const float*)d_in[0];
    const float* mask = (const float*)d_in[2];
    const float* ts   = (const float*)d_in[3];
    const float* te_w = (const float*)d_in[4];
    const float* te_b = (const float*)d_in[5];
    const float* q_w  = (const float*)d_in[6];
    const float* q_b  = (const float*)d_in[7];
    const float* k_w  = (const float*)d_in[8];
    const float* v_w  = (const float*)d_in[9];
    const float* v_b  = (const float*)d_in[10];
    const float* wih  = (const float*)d_in[11];
    const float* whh  = (const float*)d_in[12];
    const float* bih  = (const float*)d_in[13];
    const float* bhh  = (const float*)d_in[14];
    const float* mlpw = (const float*)d_in[15];
    const float* mlpb = (const float*)d_in[16];
    const float* outw = (const float*)d_in[17];
    const float* outb = (const float*)d_in[18];
    float* out = (float*)d_out;

    kQK<<<dim3(3, BATCH), 192>>>(ts, te_w, te_b, q_w, q_b, k_w);
    k2b_pack<<<800, 256>>>(v_w, v_b);
    k2_att<<<dim3(25, BATCH, 3), 256>>>(x, mask);
    k3_vgemm_bf<<<dim3(HMT/128, ROWS/128), 256>>>();
    kGI<<<NSEQ, 256>>>(wih, bih, v_w);
    k5_gru<<<NSEQ/4, 128>>>(whh, bhh, mlpw, mlpb, outw, outb, out);
}

// round 14
// speedup vs baseline: 1.8789x; 1.0220x over previous
#include <cuda_runtime.h>
#include <cuda_bf16.h>
#include <math.h>
#include <stdint.h>

#define BATCH 8
#define TT 96
#define NNODE 200
#define EMB 32
#define HID 32
#define HOR 24
#define FV 400
#define KEV 200
#define KP 208               /* KEV padded to 16 */
#define NSEQ (BATCH*NNODE)   /* 1600 */
#define ROWS (BATCH*TT)      /* 768  */
#define HMT 6400

// ---- scratch (static device globals; no allocations allowed) ----
__device__ float g_E[ROWS*TT];
__device__ __nv_bfloat16 g_attH[ROWS*KP];   // attention hi split
__device__ __nv_bfloat16 g_attL[ROWS*KP];   // attention lo split
__device__ __nv_bfloat16 g_vweH[HMT*KP];    // even v_w cols hi split (2.7MB)
__device__ __nv_bfloat16 g_vweL[HMT*KP];    // lo split
__device__ int   g_zf[BATCH*NNODE];         // per-(b,n) all-masked flag
__device__ float g_colsum[HMT];             // vb + sum of odd v_w columns
__device__ float g_Y[ROWS*HMT];             // mtan output, 19.6 MB
__device__ float g_GI[NSEQ*TT*96];          // gi gates, [seq][t][96], 59 MB

__device__ __forceinline__ float sigf(float x){ return 1.0f/(1.0f + __expf(-x)); }
__device__ __forceinline__ float ftanh(float x){ return 2.0f*sigf(2.0f*x) - 1.0f; }

__device__ __forceinline__ void mma_bf16(float& d0,float& d1,float& d2,float& d3,
    uint32_t a0,uint32_t a1,uint32_t a2,uint32_t a3, uint32_t b0,uint32_t b1){
    asm volatile("mma.sync.aligned.m16n8k16.row.col.f32.bf16.bf16.f32 "
        "{%0,%1,%2,%3}, {%4,%5,%6,%7}, {%8,%9}, {%0,%1,%2,%3};\n"
        : "+f"(d0),"+f"(d1),"+f"(d2),"+f"(d3)
        : "r"(a0),"r"(a1),"r"(a2),"r"(a3), "r"(b0),"r"(b1));
}

#define CP_ASYNC16(dst, src) \
    asm volatile("cp.async.cg.shared.global [%0], [%1], 16;\n" \
        :: "r"(dst), "l"(src))
#define CP_COMMIT() asm volatile("cp.async.commit_group;\n")
#define CP_WAIT(n)  asm volatile("cp.async.wait_group %0;\n" :: "n"(n))

// ---------------------------------------------------------------------------
// KQK: fused time-embedding + q/k projection + scores + row-max + E.
// grid=(3, 8) = (32-query slice, batch), 192 threads.
// ---------------------------------------------------------------------------
__global__ void __launch_bounds__(192)
kQK(const float* __restrict__ ts, const float* __restrict__ te_w,
    const float* __restrict__ te_b, const float* __restrict__ q_w,
    const float* __restrict__ q_b, const float* __restrict__ k_w){
    int b = blockIdx.y, q0 = blockIdx.x*32;
    int tid = threadIdx.x;
    __shared__ float te_s[TT][33];
    __shared__ float ks_s[TT][33];
    __shared__ float qs[32][33];
    __shared__ float sc[32][97];

    for (int idx = tid; idx < TT*EMB; idx += 192){
        int row = idx >> 5, e = idx & 31;
        float v = ts[b*TT+row]*te_w[e] + te_b[e];
        if (e > 0) v = sinf(v);
        te_s[row][e] = v;
    }
    __syncthreads();
    for (int idx = tid; idx < TT*EMB; idx += 192){
        int row = idx >> 5, e = idx & 31;
        float k = 0.f;
        #pragma unroll
        for (int i=0;i<EMB;i++) k = fmaf(te_s[row][i], k_w[e*EMB+i], k);
        ks_s[row][e] = k;
    }
    for (int idx = tid; idx < 32*EMB; idx += 192){
        int row = idx >> 5, e = idx & 31;
        float q = q_b[e];
        #pragma unroll
        for (int i=0;i<EMB;i++) q = fmaf(te_s[q0+row][i], q_w[e*EMB+i], q);
        qs[row][e] = q;
    }
    __syncthreads();
    for (int idx = tid; idx < 32*TT; idx += 192){
        int qq = idx / TT, kk = idx - qq*TT;
        float s = 0.f;
        #pragma unroll
        for (int i=0;i<EMB;i++) s = fmaf(qs[qq][i], ks_s[kk][i], s);
        sc[qq][kk] = s * 0.17677669529663687f;
    }
    __syncthreads();
    int w = tid>>5, lane = tid&31;
    for (int r = w; r < 32; r += 6){
        float s0 = sc[r][lane], s1 = sc[r][lane+32], s2 = sc[r][lane+64];
        float m = fmaxf(s0, fmaxf(s1, s2));
        #pragma unroll
        for (int o=16;o;o>>=1) m = fmaxf(m, __shfl_xor_sync(0xffffffffu, m, o));
        float* er = g_E + ((size_t)b*TT + q0 + r)*TT;
        er[lane]    = __expf(s0 - m);
        er[lane+32] = __expf(s1 - m);
        er[lane+64] = __expf(s2 - m);
    }
}

// ---------------------------------------------------------------------------
// K2: masked softmax aggregation, query-split for occupancy.
// grid=(25, 8, 3). Warp w = node n0+w, lane = one query.
// ---------------------------------------------------------------------------
__global__ void __launch_bounds__(256)
k2_att(const float* __restrict__ x, const float* __restrict__ mask){
    int b = blockIdx.y, n0 = blockIdx.x*8, q0 = blockIdx.z*32;
    int tid = threadIdx.x, w = tid>>5, lane = tid&31;
    int n = n0 + w;
    __shared__ float Es[32][97];
    __shared__ float xs[TT][9];
    __shared__ float ms[TT][9];
    __shared__ float ssx[8];
    const float* xb = x    + (size_t)b*TT*NNODE + n0;
    const float* mb = mask + (size_t)b*TT*NNODE + n0;
    for (int idx = tid; idx < TT*8; idx += 256){
        int t = idx>>3, i = idx&7;
        xs[t][i] = xb[t*NNODE + i];
        ms[t][i] = mb[t*NNODE + i];
    }
    for (int q=w; q<32; q+=8){
        const float* er = g_E + ((size_t)b*TT + q0 + q)*TT;
        Es[q][lane]    = er[lane];
        Es[q][lane+32] = er[lane+32];
        Es[q][lane+64] = er[lane+64];
    }
    __syncthreads();
    float sx = 0.f;
    #pragma unroll
    for (int t=lane; t<TT; t+=32) sx += xs[t][w];
    #pragma unroll
    for (int o=16;o;o>>=1) sx += __shfl_xor_sync(0xffffffffu, sx, o);
    if (lane==0) ssx[w] = sx;
    __syncwarp();

    float num=0.f, den=0.f;
    #pragma unroll 4
    for (int k=0;k<TT;k++){
        float mm = ms[k][w];
        float mx = mm * xs[k][w];
        float e  = Es[lane][k];
        den += e*mm;
        num  = fmaf(e, mx, num);
    }
    bool nz = (den > 0.f);
    float v = nz ? num/den : ssx[w]*(1.0f/96.0f);
    __nv_bfloat16 hi = __float2bfloat16(v);
    __nv_bfloat16 lo = __float2bfloat16(v - __bfloat162float(hi));
    size_t row = (size_t)b*TT + q0 + lane;
    g_attH[row*KP + n] = hi;
    g_attL[row*KP + n] = lo;
    if (lane==0 && blockIdx.z==0) g_zf[b*NNODE + n] = nz ? 0 : 1;
}

// ---------------------------------------------------------------------------
// K2b: pack even v_w columns as bf16 hi/lo splits; colsum = vb + sum(odd).
// Warps j<768 additionally zero the K-pad columns of att row j.
// ---------------------------------------------------------------------------
__global__ void k2b_pack(const float* __restrict__ vw, const float* __restrict__ vb){
    int j = (blockIdx.x*256 + threadIdx.x) >> 5;
    int lane = threadIdx.x & 31;
    const float4* src = (const float4*)(vw + (size_t)j*FV);
    float os = 0.f;
    #pragma unroll
    for (int c=lane; c<100; c+=32){
        float4 v = src[c];
        __nv_bfloat16 h0 = __float2bfloat16(v.x);
        __nv_bfloat16 h1 = __float2bfloat16(v.z);
        g_vweH[(size_t)j*KP + 2*c]   = h0;
        g_vweH[(size_t)j*KP + 2*c+1] = h1;
        g_vweL[(size_t)j*KP + 2*c]   = __float2bfloat16(v.x - __bfloat162float(h0));
        g_vweL[(size_t)j*KP + 2*c+1] = __float2bfloat16(v.z - __bfloat162float(h1));
        os += v.y + v.w;
    }
    if (lane < 8){
        g_vweH[(size_t)j*KP + 200 + lane] = __float2bfloat16(0.f);
        g_vweL[(size_t)j*KP + 200 + lane] = __float2bfloat16(0.f);
    }
    if (j < ROWS){
        if (lane < 8)       g_attH[(size_t)j*KP + 200 + lane] = __float2bfloat16(0.f);
        else if (lane < 16) g_attL[(size_t)j*KP + 200 + (lane-8)] = __float2bfloat16(0.f);
    }
    #pragma unroll
    for (int o=16;o;o>>=1) os += __shfl_xor_sync(0xffffffffu, os, o);
    if (lane == 0) g_colsum[j] = vb[j] + os;
}

// ---------------------------------------------------------------------------
// K3: Y[768x6400] = att[768x208] @ vwe[6400x208]^T + colsum
// bf16 3-term split GEMM. cp.async DOUBLE-buffered dynamic smem pipeline.
// 128x128 tile, BK=16 (13 chunks). 8 warps, 64x32 warp tile, 2 CTAs/SM.
// ---------------------------------------------------------------------------
#define K3_SMEM (8*1536*4 + 128*4)   /* 2 stages x 4 arrays x 128x12 u32 + csh */
__global__ void __launch_bounds__(256,2)
k3_vgemm_bf(){
    extern __shared__ uint32_t dsm[];
    uint32_t* AsH = dsm;               // [2][128*12]
    uint32_t* AsL = dsm + 2*1536;
    uint32_t* BsH = dsm + 4*1536;
    uint32_t* BsL = dsm + 6*1536;
    float*    csh = (float*)(dsm + 8*1536);

    int tid = threadIdx.x;
    int bn = blockIdx.x, bm = blockIdx.y;
    int warp = tid>>5, lane = tid&31;
    int wm = warp>>2, wn = warp&3;          // 2 x 4 warp grid
    int g = lane>>2, c = lane&3;

    int lrow = tid>>1;                      // 0..127
    int half = tid&1;                       // 16B quad within 32B k-chunk row

    const uint4* AgH = (const uint4*)(g_attH + (size_t)(bm*128 + lrow)*KP);
    const uint4* AgL = (const uint4*)(g_attL + (size_t)(bm*128 + lrow)*KP);
    const uint4* BgH = (const uint4*)(g_vweH + (size_t)(bn*128 + lrow)*KP);
    const uint4* BgL = (const uint4*)(g_vweL + (size_t)(bn*128 + lrow)*KP);

    if (tid < 128) csh[tid] = g_colsum[bn*128 + tid];

    // per-thread smem destinations (one 16B quad per array per stage)
    uint32_t off = (lrow*12 + half*4)*4;    // byte offset within a stage
    uint32_t dAH0 = (uint32_t)__cvta_generic_to_shared(AsH) + off;
    uint32_t dAL0 = (uint32_t)__cvta_generic_to_shared(AsL) + off;
    uint32_t dBH0 = (uint32_t)__cvta_generic_to_shared(BsH) + off;
    uint32_t dBL0 = (uint32_t)__cvta_generic_to_shared(BsL) + off;

    // prologue: stage 0 <- chunk 0
    CP_ASYNC16(dAH0, AgH + half);
    CP_ASYNC16(dAL0, AgL + half);
    CP_ASYNC16(dBH0, BgH + half);
    CP_ASYNC16(dBL0, BgL + half);
    CP_COMMIT();

    float acc[4][4][4];
    #pragma unroll
    for (int i=0;i<4;i++)
        #pragma unroll
        for (int j=0;j<4;j++)
            #pragma unroll
            for (int r=0;r<4;r++) acc[i][j][r]=0.f;

    #pragma unroll 1
    for (int it=0; it<13; ++it){
        // issue next chunk into the spare stage
        if (it < 12){
            uint32_t soff = ((it+1)&1) * 6144;      // stage byte offset
            CP_ASYNC16(dAH0 + soff, AgH + (it+1)*2 + half);
            CP_ASYNC16(dAL0 + soff, AgL + (it+1)*2 + half);
            CP_ASYNC16(dBH0 + soff, BgH + (it+1)*2 + half);
            CP_ASYNC16(dBL0 + soff, BgL + (it+1)*2 + half);
            CP_COMMIT();
            CP_WAIT(1);                             // current stage ready
        } else {
            CP_WAIT(0);
        }
        __syncthreads();

        int base = (it&1)*1536;
        uint32_t aH[4][4], aL[4][4], bH[4][2], bL[4][2];
        #pragma unroll
        for (int mt=0; mt<4; mt++){
            int rb = wm*64 + mt*16 + g;
            aH[mt][0]=AsH[base+rb*12+c];       aH[mt][1]=AsH[base+(rb+8)*12+c];
            aH[mt][2]=AsH[base+rb*12+c+4];     aH[mt][3]=AsH[base+(rb+8)*12+c+4];
            aL[mt][0]=AsL[base+rb*12+c];       aL[mt][1]=AsL[base+(rb+8)*12+c];
            aL[mt][2]=AsL[base+rb*12+c+4];     aL[mt][3]=AsL[base+(rb+8)*12+c+4];
        }
        #pragma unroll
        for (int nt=0; nt<4; nt++){
            int nb = wn*32 + nt*8 + g;
            bH[nt][0]=BsH[base+nb*12+c]; bH[nt][1]=BsH[base+nb*12+c+4];
            bL[nt][0]=BsL[base+nb*12+c]; bL[nt][1]=BsL[base+nb*12+c+4];
        }
        #pragma unroll
        for (int mt=0; mt<4; mt++)
            #pragma unroll
            for (int nt=0; nt<4; nt++){
                float* d = acc[mt][nt];
                mma_bf16(d[0],d[1],d[2],d[3],
                         aH[mt][0],aH[mt][1],aH[mt][2],aH[mt][3],
                         bL[nt][0],bL[nt][1]);
                mma_bf16(d[0],d[1],d[2],d[3],
                         aL[mt][0],aL[mt][1],aL[mt][2],aL[mt][3],
                         bH[nt][0],bH[nt][1]);
                mma_bf16(d[0],d[1],d[2],d[3],
                         aH[mt][0],aH[mt][1],aH[mt][2],aH[mt][3],
                         bH[nt][0],bH[nt][1]);
            }
        __syncthreads();    // all reads of this stage done before it is re-filled
    }

    #pragma unroll
    for (int mt=0; mt<4; mt++){
        #pragma unroll
        for (int nt=0; nt<4; nt++){
            int colL = wn*32 + nt*8 + 2*c;
            int col  = bn*128 + colL;
            float cs0 = csh[colL], cs1 = csh[colL+1];
            int r0 = bm*128 + wm*64 + mt*16 + g;
            float* d = acc[mt][nt];
            *(float2*)(g_Y + (size_t)r0*HMT + col) =
                make_float2(d[0]+cs0, d[1]+cs1);
            *(float2*)(g_Y + (size_t)(r0+8)*HMT + col) =
                make_float2(d[2]+cs0, d[3]+cs1);
        }
    }
}

// ---------------------------------------------------------------------------
// KGI: input-gate projection. block = one seq, 8 warps x 12-step chunks.
// wih staged via padded smem -> coalesced global load + conflict-free LDS.
// ---------------------------------------------------------------------------
#define TCH 12
__global__ void __launch_bounds__(256)
kGI(const float* __restrict__ wih, const float* __restrict__ bih,
    const float* __restrict__ vw){
    __shared__ float wsh[96][33];       // 12.4 KB, padded
    int tid = threadIdx.x;
    for (int idx = tid; idx < 96*32; idx += 256)
        wsh[idx>>5][idx&31] = wih[idx];
    __syncthreads();

    int w = tid>>5, j = tid&31;
    int seq = blockIdx.x;
    int t0  = w * TCH;
    int b = seq / NNODE, n = seq % NNODE;

    float wr[32], wz[32], wn[32];
    #pragma unroll
    for (int i=0;i<32;i++){
        wr[i] = wsh[j][i];
        wz[i] = wsh[32+j][i];
        wn[i] = wsh[64+j][i];
    }

    // all-masked-node correction (exact; probability ~2^-96 per node)
    float c0=0.f, c1=0.f, c2=0.f;
    {
        int anyz = 0;
        for (int i=j; i<NNODE; i+=32) anyz |= g_zf[b*NNODE+i];
        anyz = __reduce_or_sync(0xffffffffu, anyz);
        if (anyz){
            for (int n0=0;n0<NNODE;n0++){
                if (g_zf[b*NNODE+n0]){
                    #pragma unroll
                    for (int i=0;i<32;i++){
                        float vv = vw[((size_t)n*32+i)*FV + 2*n0 + 1];
                        c0 = fmaf(wr[i], vv, c0);
                        c1 = fmaf(wz[i], vv, c1);
                        c2 = fmaf(wn[i], vv, c2);
                    }
                }
            }
        }
    }
    float br  = bih[j]    - c0;
    float bz  = bih[32+j] - c1;
    float bnn = bih[64+j] - c2;

    const float* xb = g_Y + (size_t)b*TT*HMT + n*HID + j + (size_t)t0*HMT;
    float* gp = g_GI + (size_t)seq*TT*96 + t0*96;

    float xq[2];
    xq[0] = xb[0];
    xq[1] = xb[HMT];

    #pragma unroll
    for (int t=0;t<TCH;t++){
        float xc = xq[t&1];
        if (t+2 < TCH) xq[t&1] = xb[(size_t)(t+2)*HMT];
        float gr=br, gz=bz, gn=bnn;
        #pragma unroll
        for (int i=0;i<32;i++){
            float xv = __shfl_sync(0xffffffffu, xc, i);
            gr = fmaf(wr[i], xv, gr);
            gz = fmaf(wz[i], xv, gz);
            gn = fmaf(wn[i], xv, gn);
        }
        gp[t*96 +      j] = gr;
        gp[t*96 + 32 + j] = gz;
        gp[t*96 + 64 + j] = gn;
    }
}

// ---------------------------------------------------------------------------
// K5: lean GRU recurrence + fused MLP decoder.
// whh staged via padded smem (coalesced + conflict-free).
// ---------------------------------------------------------------------------
__global__ void __launch_bounds__(128)
k5_gru(const float* __restrict__ whh, const float* __restrict__ bhh,
       const float* __restrict__ mlp_w, const float* __restrict__ mlp_b,
       const float* __restrict__ out_w, const float* __restrict__ out_b,
       float* __restrict__ out){
    __shared__ float ush[96][33];       // 12.4 KB, padded
    int tid = threadIdx.x;
    for (int idx = tid; idx < 96*32; idx += 128)
        ush[idx>>5][idx&31] = whh[idx];
    __syncthreads();

    int wid = tid >> 5;
    int j   = tid & 31;
    int seq = blockIdx.x*4 + wid;
    int b = seq / NNODE, n = seq % NNODE;

    float ur[32], uz[32], un[32];
    #pragma unroll
    for (int i=0;i<32;i++){
        ur[i] = ush[j][i];
        uz[i] = ush[32+j][i];
        un[i] = ush[64+j][i];
    }
    float bhr = bhh[j], bhz = bhh[32+j], bhn = bhh[64+j];

    const float* gp = g_GI + (size_t)seq*TT*96;
    float a0 = gp[j], a1 = gp[32+j], a2 = gp[64+j];

    float h = 0.f;
    #pragma unroll 2
    for (int t=0;t<TT;t++){
        const float* nx = gp + ((t<TT-1)? t+1 : t)*96;
        float p0 = nx[j], p1 = nx[32+j], p2 = nx[64+j];
        float hr=0.f, hz=0.f, hn=0.f;
        #pragma unroll
        for (int i=0;i<32;i++){
            float hv = __shfl_sync(0xffffffffu, h, i);
            hr = fmaf(ur[i], hv, hr);
            hz = fmaf(uz[i], hv, hz);
            hn = fmaf(un[i], hv, hn);
        }
        float r  = sigf(a0 + hr + bhr);
        float z  = sigf(a1 + hz + bhz);
        float nn = ftanh(a2 + r*(hn + bhn));
        h = (1.f - z)*nn + z*h;
        a0 = p0; a1 = p1; a2 = p2;
    }

    float h2 = mlp_b[j];
    #pragma unroll
    for (int i=0;i<32;i++)
        h2 = fmaf(mlp_w[j*32+i], __shfl_sync(0xffffffffu, h, i), h2);
    h2 = fmaxf(h2, 0.f);

    float y = (j < HOR) ? out_b[j] : 0.f;
    #pragma unroll
    for (int i=0;i<32;i++){
        float v = __shfl_sync(0xffffffffu, h2, i);
        if (j < HOR) y = fmaf(out_w[j*32+i], v, y);
    }
    if (j < HOR) out[((size_t)b*HOR + j)*NNODE + n] = y;
}

// ---------------------------------------------------------------------------
extern "C" void kernel_launch(void* const* d_in, const int* in_sizes, int n_in,
                              void* d_out, int out_size){
    const float* x    = (const float*)d_in[0];
    const float* mask = (const float*)d_in[2];
    const float* ts   = (const float*)d_in[3];
    const float* te_w = (const float*)d_in[4];
    const float* te_b = (const float*)d_in[5];
    const float* q_w  = (const float*)d_in[6];
    const float* q_b  = (const float*)d_in[7];
    const float* k_w  = (const float*)d_in[8];
    const float* v_w  = (const float*)d_in[9];
    const float* v_b  = (const float*)d_in[10];
    const float* wih  = (const float*)d_in[11];
    const float* whh  = (const float*)d_in[12];
    const float* bih  = (const float*)d_in[13];
    const float* bhh  = (const float*)d_in[14];
    const float* mlpw = (const float*)d_in[15];
    const float* mlpb = (const float*)d_in[16];
    const float* outw = (const float*)d_in[17];
    const float* outb = (const float*)d_in[18];
    float* out = (float*)d_out;

    cudaFuncSetAttribute(k3_vgemm_bf,
        cudaFuncAttributeMaxDynamicSharedMemorySize, K3_SMEM);

    kQK<<<dim3(3, BATCH), 192>>>(ts, te_w, te_b, q_w, q_b, k_w);
    k2b_pack<<<800, 256>>>(v_w, v_b);
    k2_att<<<dim3(25, BATCH, 3), 256>>>(x, mask);
    k3_vgemm_bf<<<dim3(HMT/128, ROWS/128), 256, K3_SMEM>>>();
    kGI<<<NSEQ, 256>>>(wih, bih, v_w);
    k5_gru<<<NSEQ/4, 128>>>(whh, bhh, mlpw, mlpb, outw, outb, out);
}